// round 1
// baseline (speedup 1.0000x reference)
#include <cuda_runtime.h>

#define T_LEN 16384
#define HID 1024
#define L_CHUNK 128
#define NCHUNK 128  // T_LEN / L_CHUNK

// ---------------- scratch (static device allocations; no cudaMalloc) --------
__device__ float g_bu_re[T_LEN * HID];   // Bu real, then hidden real (in-place)
__device__ float g_bu_im[T_LEN * HID];   // Bu imag, then hidden imag (in-place)
__device__ float g_bs_re[HID * HID];     // B_re * exp(gamma)[row]
__device__ float g_bs_im[HID * HID];
__device__ float g_ct_re[HID * HID];     // C_re transposed -> [h][o]
__device__ float g_ct_im[HID * HID];
__device__ float g_lam_re[HID], g_lam_im[HID];
__device__ float g_lamL_re[HID], g_lamL_im[HID];  // lambda^L_CHUNK
__device__ float g_end_re[NCHUNK * HID], g_end_im[NCHUNK * HID];
__device__ float g_carry_re[NCHUNK * HID], g_carry_im[NCHUNK * HID];

// ---------------- prep ------------------------------------------------------
__global__ void prep_lambda(const float* __restrict__ nu_log,
                            const float* __restrict__ theta_log) {
    int h = threadIdx.x;
    float a = -expf(nu_log[h]);      // log|lambda|
    float b = expf(theta_log[h]);    // phase
    float m = expf(a);
    g_lam_re[h] = m * cosf(b);
    g_lam_im[h] = m * sinf(b);
    // lambda^L via polar form in double (phase L*b up to ~800 rad)
    double aL = (double)a * (double)L_CHUNK;
    double bL = (double)b * (double)L_CHUNK;
    double mL = exp(aL);
    g_lamL_re[h] = (float)(mL * cos(bL));
    g_lamL_im[h] = (float)(mL * sin(bL));
}

__global__ void prep_weights(const float* __restrict__ B_re,
                             const float* __restrict__ B_im,
                             const float* __restrict__ gamma_log,
                             const float* __restrict__ C_re,
                             const float* __restrict__ C_im) {
    int idx = blockIdx.x * blockDim.x + threadIdx.x;  // 0 .. HID*HID-1
    int i = idx >> 10;       // row
    int h = idx & 1023;      // col
    // Faithful to reference broadcast: gamma indexed by ROW (in_dim) since in==hid
    float g = expf(gamma_log[i]);
    g_bs_re[idx] = B_re[idx] * g;
    g_bs_im[idx] = B_im[idx] * g;
    // transpose: ct[k=i][n=h] = C[n=h][k=i]
    g_ct_re[idx] = C_re[h * HID + i];
    g_ct_im[idx] = C_im[h * HID + i];
}

// ---------------- SGEMM: C[M,N] (+)= alpha * A[M,K] @ B[K,N], all row-major --
template <int ACC>
__global__ __launch_bounds__(256, 2)
void sgemm128(const float* __restrict__ A, const float* __restrict__ B,
              float* __restrict__ C, int M, int N, int K, float alpha) {
    const int BM = 128, BN = 128, BK = 16;
    __shared__ float As[BK][BM];
    __shared__ float Bs[BK][BN];
    int tid = threadIdx.x;
    int cRow = blockIdx.y, cCol = blockIdx.x;
    const float* Ab = A + (size_t)cRow * BM * K;
    const float* Bb = B + cCol * BN;

    int tr = tid / 16, tc = tid % 16;  // 16x16 thread grid, 8x8 each
    float acc[8][8];
#pragma unroll
    for (int i = 0; i < 8; i++)
#pragma unroll
        for (int j = 0; j < 8; j++) acc[i][j] = 0.f;

    for (int k0 = 0; k0 < K; k0 += BK) {
        // load A tile (128x16) transposed into As[k][m]; 512 float4 / 256 thr
#pragma unroll
        for (int it = 0; it < 2; ++it) {
            int j = tid + it * 256;
            int row = j >> 2, c4 = j & 3;
            float4 v = *(const float4*)(Ab + (size_t)row * K + k0 + c4 * 4);
            As[c4 * 4 + 0][row] = v.x;
            As[c4 * 4 + 1][row] = v.y;
            As[c4 * 4 + 2][row] = v.z;
            As[c4 * 4 + 3][row] = v.w;
        }
        // load B tile (16x128)
#pragma unroll
        for (int it = 0; it < 2; ++it) {
            int j = tid + it * 256;
            int row = j >> 5, c4 = j & 31;
            *(float4*)(&Bs[row][c4 * 4]) =
                *(const float4*)(Bb + (size_t)(k0 + row) * N + c4 * 4);
        }
        __syncthreads();
#pragma unroll
        for (int kk = 0; kk < BK; kk++) {
            float ra[8], rb[8];
            *(float4*)(ra)     = *(const float4*)(&As[kk][tr * 8]);
            *(float4*)(ra + 4) = *(const float4*)(&As[kk][tr * 8 + 4]);
            *(float4*)(rb)     = *(const float4*)(&Bs[kk][tc * 8]);
            *(float4*)(rb + 4) = *(const float4*)(&Bs[kk][tc * 8 + 4]);
#pragma unroll
            for (int i = 0; i < 8; i++)
#pragma unroll
                for (int j = 0; j < 8; j++) acc[i][j] += ra[i] * rb[j];
        }
        __syncthreads();
    }

    float* Cb = C + (size_t)(cRow * BM + tr * 8) * N + cCol * BN + tc * 8;
#pragma unroll
    for (int i = 0; i < 8; i++) {
#pragma unroll
        for (int j = 0; j < 8; j++) {
            float v = alpha * acc[i][j];
            if (ACC) v += Cb[(size_t)i * N + j];
            Cb[(size_t)i * N + j] = v;
        }
    }
}

// ---------------- chunked complex scan --------------------------------------
// phase A: per (chunk, h) local scan from zero, record chunk-end state
__global__ void scan_ends() {
    int g = blockIdx.x * blockDim.x + threadIdx.x;  // 0 .. NCHUNK*HID-1
    int h = g & 1023, chunk = g >> 10;
    float lr = g_lam_re[h], li = g_lam_im[h];
    float sr = 0.f, si = 0.f;
    size_t base = (size_t)chunk * L_CHUNK * HID + h;
#pragma unroll 4
    for (int t = 0; t < L_CHUNK; t++) {
        float br = g_bu_re[base + (size_t)t * HID];
        float bi = g_bu_im[base + (size_t)t * HID];
        float nr = fmaf(lr, sr, fmaf(-li, si, br));
        float ni = fmaf(lr, si, fmaf(li, sr, bi));
        sr = nr; si = ni;
    }
    g_end_re[chunk * HID + h] = sr;
    g_end_im[chunk * HID + h] = si;
}

// phase B: per h, sequential carry chain across chunks using lambda^L
__global__ void scan_carries() {
    int h = blockIdx.x * blockDim.x + threadIdx.x;  // 0..1023
    float lr = g_lamL_re[h], li = g_lamL_im[h];
    float cr = 0.f, ci = 0.f;
    for (int c = 0; c < NCHUNK; c++) {
        g_carry_re[c * HID + h] = cr;
        g_carry_im[c * HID + h] = ci;
        float er = g_end_re[c * HID + h], ei = g_end_im[c * HID + h];
        float nr = fmaf(lr, cr, fmaf(-li, ci, er));
        float ni = fmaf(lr, ci, fmaf(li, cr, ei));
        cr = nr; ci = ni;
    }
}

// phase C: replay local scan seeded with carry, write hidden in-place over Bu
__global__ void scan_apply() {
    int g = blockIdx.x * blockDim.x + threadIdx.x;
    int h = g & 1023, chunk = g >> 10;
    float lr = g_lam_re[h], li = g_lam_im[h];
    float sr = g_carry_re[chunk * HID + h];
    float si = g_carry_im[chunk * HID + h];
    size_t base = (size_t)chunk * L_CHUNK * HID + h;
#pragma unroll 4
    for (int t = 0; t < L_CHUNK; t++) {
        float br = g_bu_re[base + (size_t)t * HID];
        float bi = g_bu_im[base + (size_t)t * HID];
        float nr = fmaf(lr, sr, fmaf(-li, si, br));
        float ni = fmaf(lr, si, fmaf(li, sr, bi));
        sr = nr; si = ni;
        g_bu_re[base + (size_t)t * HID] = sr;
        g_bu_im[base + (size_t)t * HID] = si;
    }
}

// ---------------- launch ----------------------------------------------------
extern "C" void kernel_launch(void* const* d_in, const int* in_sizes, int n_in,
                              void* d_out, int out_size) {
    const float* inputs    = (const float*)d_in[0];
    const float* nu_log    = (const float*)d_in[1];
    const float* theta_log = (const float*)d_in[2];
    const float* gamma_log = (const float*)d_in[3];
    const float* B_re      = (const float*)d_in[4];
    const float* B_im      = (const float*)d_in[5];
    const float* C_re      = (const float*)d_in[6];
    const float* C_im      = (const float*)d_in[7];
    const float* Dmat      = (const float*)d_in[8];
    float* out = (float*)d_out;

    // symbol addresses for generic SGEMM (host API, capture-safe)
    float *bu_re, *bu_im, *bs_re, *bs_im, *ct_re, *ct_im;
    cudaGetSymbolAddress((void**)&bu_re, g_bu_re);
    cudaGetSymbolAddress((void**)&bu_im, g_bu_im);
    cudaGetSymbolAddress((void**)&bs_re, g_bs_re);
    cudaGetSymbolAddress((void**)&bs_im, g_bs_im);
    cudaGetSymbolAddress((void**)&ct_re, g_ct_re);
    cudaGetSymbolAddress((void**)&ct_im, g_ct_im);

    prep_lambda<<<1, HID>>>(nu_log, theta_log);
    prep_weights<<<(HID * HID) / 256, 256>>>(B_re, B_im, gamma_log, C_re, C_im);

    dim3 grid(HID / 128, T_LEN / 128);
    dim3 blk(256);

    // Bu = inputs @ (B * exp(gamma))   (complex, two real GEMMs)
    sgemm128<0><<<grid, blk>>>(inputs, bs_re, bu_re, T_LEN, HID, HID, 1.0f);
    sgemm128<0><<<grid, blk>>>(inputs, bs_im, bu_im, T_LEN, HID, HID, 1.0f);

    // complex diagonal scan (3-phase, in-place)
    scan_ends<<<(NCHUNK * HID) / 256, 256>>>();
    scan_carries<<<HID / 256, 256>>>();
    scan_apply<<<(NCHUNK * HID) / 256, 256>>>();

    // out = Re(hidden @ C^T) + inputs @ D
    sgemm128<0><<<grid, blk>>>(bu_re, ct_re, out, T_LEN, HID, HID, 1.0f);
    sgemm128<1><<<grid, blk>>>(bu_im, ct_im, out, T_LEN, HID, HID, -1.0f);
    sgemm128<1><<<grid, blk>>>(inputs, Dmat, out, T_LEN, HID, HID, 1.0f);
}

// round 2
// speedup vs baseline: 3.2943x; 3.2943x over previous
#include <cuda_runtime.h>
#include <cstdint>

#define T_LEN 16384
#define HID 1024
#define HID3 3072
#define L_CHUNK 128
#define NCHUNK 128

#define BM 128
#define BN 128
#define BK 16
#define ASTR 20    // As row stride (floats): 20 mod 32 -> conflict-free frag loads
#define BSTR 136   // Bs row stride: 136 mod 32 = 8 -> conflict-free frag loads

// ---------------- scratch ----------------------------------------------------
__device__ float g_hidden[T_LEN * HID3];   // [h_re | h_im | inputs] per row
__device__ float g_bcat[HID * 2048];       // [Bs_re | Bs_im] row-major k x 2048
__device__ float g_w2[HID3 * HID];         // [Ct_re ; -Ct_im ; D]
__device__ float g_lam_re[HID], g_lam_im[HID];
__device__ float g_lamL_re[HID], g_lamL_im[HID];
__device__ float g_end_re[NCHUNK * HID], g_end_im[NCHUNK * HID];
__device__ float g_carry_re[NCHUNK * HID], g_carry_im[NCHUNK * HID];

// ---------------- prep -------------------------------------------------------
__global__ void prep_lambda(const float* __restrict__ nu_log,
                            const float* __restrict__ theta_log) {
    int h = threadIdx.x;
    float a = -expf(nu_log[h]);
    float b = expf(theta_log[h]);
    float m = expf(a);
    g_lam_re[h] = m * cosf(b);
    g_lam_im[h] = m * sinf(b);
    double aL = (double)a * (double)L_CHUNK;
    double bL = (double)b * (double)L_CHUNK;
    double mL = exp(aL);
    g_lamL_re[h] = (float)(mL * cos(bL));
    g_lamL_im[h] = (float)(mL * sin(bL));
}

__global__ void prep_bcat(const float* __restrict__ B_re,
                          const float* __restrict__ B_im,
                          const float* __restrict__ gamma_log) {
    int idx = blockIdx.x * blockDim.x + threadIdx.x;   // 0 .. HID*HID-1
    int i = idx >> 10;
    int h = idx & 1023;
    float g = expf(gamma_log[i]);                      // row broadcast (faithful)
    g_bcat[(size_t)i * 2048 + h]        = B_re[idx] * g;
    g_bcat[(size_t)i * 2048 + 1024 + h] = B_im[idx] * g;
}

__global__ void prep_w2(const float* __restrict__ C_re,
                        const float* __restrict__ C_im,
                        const float* __restrict__ D) {
    int idx = blockIdx.x * blockDim.x + threadIdx.x;   // 0 .. 3072*1024-1
    int r = idx >> 10;
    int o = idx & 1023;
    float v;
    if (r < 1024)       v =  C_re[(size_t)o * HID + r];
    else if (r < 2048)  v = -C_im[(size_t)o * HID + (r - 1024)];
    else                v =  D[(size_t)(r - 2048) * HID + o];
    g_w2[idx] = v;
}

__global__ void copy_inputs(const float* __restrict__ inputs) {
    int idx = blockIdx.x * blockDim.x + threadIdx.x;   // float4 index
    int row = idx >> 8;                                // 256 float4 per row
    int c4 = idx & 255;
    const float4 v = ((const float4*)inputs)[(size_t)row * 256 + c4];
    *(float4*)&g_hidden[(size_t)row * HID3 + 2048 + c4 * 4] = v;
}

// ---------------- TF32 tensor-core GEMM -------------------------------------
__device__ __forceinline__ uint32_t f2tf(float f) {
    uint32_t r;
    asm("cvt.rna.tf32.f32 %0, %1;" : "=r"(r) : "f"(f));
    return r;
}
__device__ __forceinline__ void cp16(void* dst, const float* src) {
    uint32_t d = (uint32_t)__cvta_generic_to_shared(dst);
    asm volatile("cp.async.cg.shared.global [%0], [%1], 16;" :: "r"(d), "l"(src));
}
__device__ __forceinline__ void mma_tf32(float* c, const uint32_t* a, const uint32_t* b) {
    asm volatile(
        "mma.sync.aligned.m16n8k8.row.col.f32.tf32.tf32.f32 "
        "{%0,%1,%2,%3},{%4,%5,%6,%7},{%8,%9},{%0,%1,%2,%3};"
        : "+f"(c[0]), "+f"(c[1]), "+f"(c[2]), "+f"(c[3])
        : "r"(a[0]), "r"(a[1]), "r"(a[2]), "r"(a[3]), "r"(b[0]), "r"(b[1]));
}

// C[M,N] = A[M,K] @ B[K,N], row-major, arbitrary leading dims, no accumulate.
__global__ __launch_bounds__(256, 2)
void tf32gemm(const float* __restrict__ A, const float* __restrict__ B,
              float* __restrict__ C, int K, int lda, int ldb, int ldc) {
    __shared__ float As[2][BM][ASTR];   // [m][k] layout
    __shared__ float Bs[2][BK][BSTR];   // [k][n] layout

    const int tid = threadIdx.x;
    const int bm = blockIdx.y * BM;
    const int bn = blockIdx.x * BN;

    // gmem->smem tile maps
    const int ar0 = tid >> 2;            // A rows 0..63 (it0), +64 (it1)
    const int ac4 = (tid & 3) * 4;       // A col (floats) 0/4/8/12
    const int br0 = tid >> 5;            // B rows 0..7 (it0), +8 (it1)
    const int bc4 = (tid & 31) * 4;      // B col (floats)

    const float* Ag = A + (size_t)(bm + ar0) * lda + ac4;
    const float* Bg = B + (size_t)br0 * ldb + bn + bc4;

    const int lane = tid & 31, wid = tid >> 5;
    const int wm = (wid >> 2) * 64;      // 2 warps along M
    const int wn = (wid & 3) * 32;       // 4 warps along N
    const int g = lane >> 2, t = lane & 3;

    float acc[4][4][4];
#pragma unroll
    for (int mt = 0; mt < 4; mt++)
#pragma unroll
        for (int nt = 0; nt < 4; nt++)
#pragma unroll
            for (int i = 0; i < 4; i++) acc[mt][nt][i] = 0.f;

    const int niter = K / BK;

    // prologue: stage tile 0
    {
        cp16(&As[0][ar0][ac4], Ag);
        cp16(&As[0][ar0 + 64][ac4], Ag + (size_t)64 * lda);
        cp16(&Bs[0][br0][bc4], Bg);
        cp16(&Bs[0][br0 + 8][bc4], Bg + (size_t)8 * ldb);
        asm volatile("cp.async.commit_group;");
    }

    for (int i = 0; i < niter; i++) {
        if (i + 1 < niter) {
            const int nb = (i + 1) & 1;
            const int k0 = (i + 1) * BK;
            const float* a = Ag + k0;
            const float* b = Bg + (size_t)k0 * ldb;
            cp16(&As[nb][ar0][ac4], a);
            cp16(&As[nb][ar0 + 64][ac4], a + (size_t)64 * lda);
            cp16(&Bs[nb][br0][bc4], b);
            cp16(&Bs[nb][br0 + 8][bc4], b + (size_t)8 * ldb);
            asm volatile("cp.async.commit_group;");
            asm volatile("cp.async.wait_group 1;");
        } else {
            asm volatile("cp.async.wait_group 0;");
        }
        __syncthreads();

        const int buf = i & 1;
#pragma unroll
        for (int ks = 0; ks < 2; ks++) {
            const int k8 = ks * 8;
            uint32_t af[4][4], bf[4][2];
#pragma unroll
            for (int mt = 0; mt < 4; mt++) {
                const float* ap = &As[buf][wm + mt * 16 + g][k8 + t];
                af[mt][0] = f2tf(ap[0]);
                af[mt][1] = f2tf(ap[8 * ASTR]);
                af[mt][2] = f2tf(ap[4]);
                af[mt][3] = f2tf(ap[8 * ASTR + 4]);
            }
#pragma unroll
            for (int nt = 0; nt < 4; nt++) {
                const float* bp = &Bs[buf][k8 + t][wn + nt * 8 + g];
                bf[nt][0] = f2tf(bp[0]);
                bf[nt][1] = f2tf(bp[4 * BSTR]);
            }
#pragma unroll
            for (int mt = 0; mt < 4; mt++)
#pragma unroll
                for (int nt = 0; nt < 4; nt++)
                    mma_tf32(acc[mt][nt], af[mt], bf[nt]);
        }
        __syncthreads();
    }

    // epilogue
    float* Cb = C + (size_t)(bm + wm) * ldc + bn + wn;
#pragma unroll
    for (int mt = 0; mt < 4; mt++) {
#pragma unroll
        for (int nt = 0; nt < 4; nt++) {
            const int r0 = mt * 16 + g;
            const int c0 = nt * 8 + t * 2;
            *(float2*)&Cb[(size_t)r0 * ldc + c0] =
                make_float2(acc[mt][nt][0], acc[mt][nt][1]);
            *(float2*)&Cb[(size_t)(r0 + 8) * ldc + c0] =
                make_float2(acc[mt][nt][2], acc[mt][nt][3]);
        }
    }
}

// ---------------- chunked complex scan (in-place on g_hidden cols 0..2047) ---
__global__ void scan_ends() {
    int gidx = blockIdx.x * blockDim.x + threadIdx.x;
    int h = gidx & 1023, chunk = gidx >> 10;
    float lr = g_lam_re[h], li = g_lam_im[h];
    float sr = 0.f, si = 0.f;
    size_t base = (size_t)chunk * L_CHUNK * HID3 + h;
#pragma unroll 4
    for (int tt = 0; tt < L_CHUNK; tt++) {
        float br = g_hidden[base + (size_t)tt * HID3];
        float bi = g_hidden[base + (size_t)tt * HID3 + 1024];
        float nr = fmaf(lr, sr, fmaf(-li, si, br));
        float ni = fmaf(lr, si, fmaf(li, sr, bi));
        sr = nr; si = ni;
    }
    g_end_re[chunk * HID + h] = sr;
    g_end_im[chunk * HID + h] = si;
}

__global__ void scan_carries() {
    int h = blockIdx.x * blockDim.x + threadIdx.x;
    float lr = g_lamL_re[h], li = g_lamL_im[h];
    float cr = 0.f, ci = 0.f;
    for (int c = 0; c < NCHUNK; c++) {
        g_carry_re[c * HID + h] = cr;
        g_carry_im[c * HID + h] = ci;
        float er = g_end_re[c * HID + h], ei = g_end_im[c * HID + h];
        float nr = fmaf(lr, cr, fmaf(-li, ci, er));
        float ni = fmaf(lr, ci, fmaf(li, cr, ei));
        cr = nr; ci = ni;
    }
}

__global__ void scan_apply() {
    int gidx = blockIdx.x * blockDim.x + threadIdx.x;
    int h = gidx & 1023, chunk = gidx >> 10;
    float lr = g_lam_re[h], li = g_lam_im[h];
    float sr = g_carry_re[chunk * HID + h];
    float si = g_carry_im[chunk * HID + h];
    size_t base = (size_t)chunk * L_CHUNK * HID3 + h;
#pragma unroll 4
    for (int tt = 0; tt < L_CHUNK; tt++) {
        float br = g_hidden[base + (size_t)tt * HID3];
        float bi = g_hidden[base + (size_t)tt * HID3 + 1024];
        float nr = fmaf(lr, sr, fmaf(-li, si, br));
        float ni = fmaf(lr, si, fmaf(li, sr, bi));
        sr = nr; si = ni;
        g_hidden[base + (size_t)tt * HID3] = sr;
        g_hidden[base + (size_t)tt * HID3 + 1024] = si;
    }
}

// ---------------- launch -----------------------------------------------------
extern "C" void kernel_launch(void* const* d_in, const int* in_sizes, int n_in,
                              void* d_out, int out_size) {
    const float* inputs    = (const float*)d_in[0];
    const float* nu_log    = (const float*)d_in[1];
    const float* theta_log = (const float*)d_in[2];
    const float* gamma_log = (const float*)d_in[3];
    const float* B_re      = (const float*)d_in[4];
    const float* B_im      = (const float*)d_in[5];
    const float* C_re      = (const float*)d_in[6];
    const float* C_im      = (const float*)d_in[7];
    const float* Dmat      = (const float*)d_in[8];
    float* out = (float*)d_out;

    float *hidden, *bcat, *w2;
    cudaGetSymbolAddress((void**)&hidden, g_hidden);
    cudaGetSymbolAddress((void**)&bcat, g_bcat);
    cudaGetSymbolAddress((void**)&w2, g_w2);

    prep_lambda<<<1, HID>>>(nu_log, theta_log);
    prep_bcat<<<(HID * HID) / 256, 256>>>(B_re, B_im, gamma_log);
    prep_w2<<<(HID3 * HID) / 256, 256>>>(C_re, C_im, Dmat);
    copy_inputs<<<(T_LEN * HID / 4) / 256, 256>>>(inputs);

    // GEMM1: Bu(re|im) = inputs @ bcat   [16384,1024]x[1024,2048] -> hidden[:, :2048]
    tf32gemm<<<dim3(2048 / BN, T_LEN / BM), 256>>>(
        inputs, bcat, hidden, HID, HID, 2048, HID3);

    // complex diagonal scan, in-place
    scan_ends<<<(NCHUNK * HID) / 256, 256>>>();
    scan_carries<<<HID / 256, 256>>>();
    scan_apply<<<(NCHUNK * HID) / 256, 256>>>();

    // GEMM2: out = [h_re|h_im|inputs] @ [Ct_re; -Ct_im; D]   [16384,3072]x[3072,1024]
    tf32gemm<<<dim3(HID / BN, T_LEN / BM), 256>>>(
        hidden, w2, out, HID3, HID3, HID, HID);
}

// round 4
// speedup vs baseline: 3.6062x; 1.0947x over previous
#include <cuda_runtime.h>
#include <cstdint>

#define T_LEN 16384
#define HID 1024
#define HID3 3072
#define L_CHUNK 128
#define NCHUNK 128

#define BM 128
#define BN 128
#define BK 32
#define ASTR 36    // As row stride (floats): g*36+t mod 32 = g*4+t -> conflict-free
#define BSTR 136   // Bs row stride: t*136+g mod 32 = t*8+g -> conflict-free
#define STAGE_FLOATS (BM * ASTR + BK * BSTR)
#define SMEM_BYTES (2 * STAGE_FLOATS * 4)

// ---------------- scratch ----------------------------------------------------
__device__ float g_hidden[T_LEN * HID3];   // [h_re | h_im | inputs(rna)] rows
__device__ float g_bcat[HID * 2048];       // [k][n] rna'd: n<1024 re, else im
__device__ float g_w2[HID3 * HID];         // [k][o] rna'd: [Ct_re ; -Ct_im ; D]
__device__ float g_lam_re[HID], g_lam_im[HID];
__device__ float g_lamL_re[HID], g_lamL_im[HID];
__device__ float g_end_re[NCHUNK * HID], g_end_im[NCHUNK * HID];
__device__ float g_carry_re[NCHUNK * HID], g_carry_im[NCHUNK * HID];

// ---------------- helpers ----------------------------------------------------
__device__ __forceinline__ float rna_tf32(float f) {
    uint32_t r;
    asm("cvt.rna.tf32.f32 %0, %1;" : "=r"(r) : "f"(f));
    return __uint_as_float(r);
}
__device__ __forceinline__ void cp16(void* dst, const float* src) {
    uint32_t d = (uint32_t)__cvta_generic_to_shared(dst);
    asm volatile("cp.async.cg.shared.global [%0], [%1], 16;" :: "r"(d), "l"(src));
}
__device__ __forceinline__ void mma_tf32(float* c, const uint32_t* a, const uint32_t* b) {
    asm volatile(
        "mma.sync.aligned.m16n8k8.row.col.f32.tf32.tf32.f32 "
        "{%0,%1,%2,%3},{%4,%5,%6,%7},{%8,%9},{%0,%1,%2,%3};"
        : "+f"(c[0]), "+f"(c[1]), "+f"(c[2]), "+f"(c[3])
        : "r"(a[0]), "r"(a[1]), "r"(a[2]), "r"(a[3]), "r"(b[0]), "r"(b[1]));
}

// ---------------- prep -------------------------------------------------------
__global__ void prep_lambda(const float* __restrict__ nu_log,
                            const float* __restrict__ theta_log) {
    int h = threadIdx.x;
    float a = -expf(nu_log[h]);
    float b = expf(theta_log[h]);
    float m = expf(a);
    g_lam_re[h] = m * cosf(b);
    g_lam_im[h] = m * sinf(b);
    double aL = (double)a * (double)L_CHUNK;
    double bL = (double)b * (double)L_CHUNK;
    double mL = exp(aL);
    g_lamL_re[h] = (float)(mL * cos(bL));
    g_lamL_im[h] = (float)(mL * sin(bL));
}

__global__ void prep_bcat(const float* __restrict__ B_re,
                          const float* __restrict__ B_im,
                          const float* __restrict__ gamma_log) {
    int idx = blockIdx.x * blockDim.x + threadIdx.x;  // 0 .. HID*HID-1
    int k = idx >> 10, n = idx & 1023;
    float g = expf(gamma_log[k]);                     // row broadcast (faithful)
    g_bcat[(size_t)k * 2048 + n]        = rna_tf32(B_re[idx] * g);
    g_bcat[(size_t)k * 2048 + 1024 + n] = rna_tf32(B_im[idx] * g);
}

__global__ void prep_w2(const float* __restrict__ C_re,
                        const float* __restrict__ C_im,
                        const float* __restrict__ D) {
    int idx = blockIdx.x * blockDim.x + threadIdx.x;  // 0 .. 3072*1024-1
    int r = idx >> 10, o = idx & 1023;
    float v;
    if (r < 1024)       v =  C_re[(size_t)o * HID + r];
    else if (r < 2048)  v = -C_im[(size_t)o * HID + (r - 1024)];
    else                v =  D[(size_t)(r - 2048) * HID + o];
    g_w2[idx] = rna_tf32(v);
}

__global__ void copy_inputs(const float* __restrict__ inputs) {
    int idx = blockIdx.x * blockDim.x + threadIdx.x;
    int row = idx >> 8, c4 = idx & 255;
    float4 v = ((const float4*)inputs)[(size_t)row * 256 + c4];
    v.x = rna_tf32(v.x); v.y = rna_tf32(v.y);
    v.z = rna_tf32(v.z); v.w = rna_tf32(v.w);
    *(float4*)&g_hidden[(size_t)row * HID3 + 2048 + c4 * 4] = v;
}

// ---------------- TF32 tensor-core GEMM (operands pre-rounded to tf32) -------
// C[M,N] = A[M,K] @ B[K,N], row-major; leading dims lda/ldb/ldc.
__global__ __launch_bounds__(256, 2)
void tf32gemm(const float* __restrict__ A, const float* __restrict__ B,
              float* __restrict__ C, int K, int lda, int ldb, int ldc) {
    extern __shared__ float smem[];
    float (*As)[ASTR] = (float (*)[ASTR])smem;                      // [2*BM][ASTR]
    float (*Bs)[BSTR] = (float (*)[BSTR])(smem + 2 * BM * ASTR);    // [2*BK][BSTR]

    const int tid = threadIdx.x;
    const int bm = blockIdx.y * BM;
    const int bn = blockIdx.x * BN;

    // gmem->smem maps: 1024 float4 per tile per operand, 4 per thread
    const int ar = tid >> 1;             // A rows (2 float4 per row of 32 floats)
    const int ac4 = (tid & 1) * 4;       // A col float4 slot 0 or 4 (of 8)
    const int br = tid >> 5;             // B rows 0..7 (+8,+16,+24)
    const int bc4 = (tid & 31) * 4;

    const float* Ag = A + (size_t)(bm + ar) * lda + ac4 * 4;  // wait: recompute below
    // correct: each row has 8 float4 (32 floats). thread covers (tid&1)? Need 2
    // threads per row * 128 rows = 256 -> 2 float4 each per half. Simpler map:
    // j = tid + t*256, row = j>>3, c4 = j&7.
    (void)Ag;

    const int lane = tid & 31, wid = tid >> 5;
    const int wm = (wid >> 2) * 64;
    const int wn = (wid & 3) * 32;
    const int g = lane >> 2, t = lane & 3;

    float acc[4][4][4];
#pragma unroll
    for (int mt = 0; mt < 4; mt++)
#pragma unroll
        for (int nt = 0; nt < 4; nt++)
#pragma unroll
            for (int i = 0; i < 4; i++) acc[mt][nt][i] = 0.f;

    const int niter = K / BK;

#define LOAD_STAGE(buf, it)                                                   \
    {                                                                         \
        _Pragma("unroll")                                                     \
        for (int tt = 0; tt < 4; tt++) {                                      \
            int j = tid + tt * 256;                                           \
            int row = j >> 3, c4 = j & 7;                                     \
            cp16(&As[(buf) * BM + row][c4 * 4],                               \
                 A + (size_t)(bm + row) * lda + (it) * BK + c4 * 4);          \
        }                                                                     \
        _Pragma("unroll")                                                     \
        for (int tt = 0; tt < 4; tt++) {                                      \
            int j = tid + tt * 256;                                           \
            int krow = j >> 5, c4 = j & 31;                                   \
            cp16(&Bs[(buf) * BK + krow][c4 * 4],                              \
                 B + (size_t)((it) * BK + krow) * ldb + bn + c4 * 4);         \
        }                                                                     \
        asm volatile("cp.async.commit_group;");                               \
    }

    LOAD_STAGE(0, 0)

    for (int i = 0; i < niter; i++) {
        if (i + 1 < niter) {
            LOAD_STAGE((i + 1) & 1, i + 1)
            asm volatile("cp.async.wait_group 1;");
        } else {
            asm volatile("cp.async.wait_group 0;");
        }
        __syncthreads();

        const int abase = (i & 1) * BM;
        const int bbase = (i & 1) * BK;
#pragma unroll
        for (int ks = 0; ks < 4; ks++) {
            const int k8 = ks * 8;
            uint32_t af[4][4], bf[4][2];
#pragma unroll
            for (int mt = 0; mt < 4; mt++) {
                const uint32_t* ap =
                    (const uint32_t*)&As[abase + wm + mt * 16 + g][k8 + t];
                af[mt][0] = ap[0];
                af[mt][1] = ap[8 * ASTR];
                af[mt][2] = ap[4];
                af[mt][3] = ap[8 * ASTR + 4];
            }
#pragma unroll
            for (int nt = 0; nt < 4; nt++) {
                const uint32_t* bp =
                    (const uint32_t*)&Bs[bbase + k8 + t][wn + nt * 8 + g];
                bf[nt][0] = bp[0];
                bf[nt][1] = bp[4 * BSTR];
            }
#pragma unroll
            for (int mt = 0; mt < 4; mt++)
#pragma unroll
                for (int nt = 0; nt < 4; nt++)
                    mma_tf32(acc[mt][nt], af[mt], bf[nt]);
        }
        __syncthreads();
    }
#undef LOAD_STAGE

    float* Cb = C + (size_t)(bm + wm) * ldc + bn + wn;
#pragma unroll
    for (int mt = 0; mt < 4; mt++) {
#pragma unroll
        for (int nt = 0; nt < 4; nt++) {
            const int r0 = mt * 16 + g;
            const int c0 = nt * 8 + t * 2;
            *(float2*)&Cb[(size_t)r0 * ldc + c0] =
                make_float2(acc[mt][nt][0], acc[mt][nt][1]);
            *(float2*)&Cb[(size_t)(r0 + 8) * ldc + c0] =
                make_float2(acc[mt][nt][2], acc[mt][nt][3]);
        }
    }
}

// ---------------- chunked complex scan (in-place on g_hidden cols 0..2047) ---
__global__ void scan_ends() {
    int gidx = blockIdx.x * blockDim.x + threadIdx.x;
    int h = gidx & 1023, chunk = gidx >> 10;
    float lr = g_lam_re[h], li = g_lam_im[h];
    float sr = 0.f, si = 0.f;
    size_t base = (size_t)chunk * L_CHUNK * HID3 + h;
#pragma unroll 4
    for (int tt = 0; tt < L_CHUNK; tt++) {
        float br = g_hidden[base + (size_t)tt * HID3];
        float bi = g_hidden[base + (size_t)tt * HID3 + 1024];
        float nr = fmaf(lr, sr, fmaf(-li, si, br));
        float ni = fmaf(lr, si, fmaf(li, sr, bi));
        sr = nr; si = ni;
    }
    g_end_re[chunk * HID + h] = sr;
    g_end_im[chunk * HID + h] = si;
}

__global__ void scan_carries() {
    int h = blockIdx.x * blockDim.x + threadIdx.x;
    float lr = g_lamL_re[h], li = g_lamL_im[h];
    float cr = 0.f, ci = 0.f;
    for (int c = 0; c < NCHUNK; c++) {
        g_carry_re[c * HID + h] = cr;
        g_carry_im[c * HID + h] = ci;
        float er = g_end_re[c * HID + h], ei = g_end_im[c * HID + h];
        float nr = fmaf(lr, cr, fmaf(-li, ci, er));
        float ni = fmaf(lr, ci, fmaf(li, cr, ei));
        cr = nr; ci = ni;
    }
}

__global__ void scan_apply() {
    int gidx = blockIdx.x * blockDim.x + threadIdx.x;
    int h = gidx & 1023, chunk = gidx >> 10;
    float lr = g_lam_re[h], li = g_lam_im[h];
    float sr = g_carry_re[chunk * HID + h];
    float si = g_carry_im[chunk * HID + h];
    size_t base = (size_t)chunk * L_CHUNK * HID3 + h;
#pragma unroll 4
    for (int tt = 0; tt < L_CHUNK; tt++) {
        float br = g_hidden[base + (size_t)tt * HID3];
        float bi = g_hidden[base + (size_t)tt * HID3 + 1024];
        float nr = fmaf(lr, sr, fmaf(-li, si, br));
        float ni = fmaf(lr, si, fmaf(li, sr, bi));
        sr = nr; si = ni;
        g_hidden[base + (size_t)tt * HID3]        = rna_tf32(sr);
        g_hidden[base + (size_t)tt * HID3 + 1024] = rna_tf32(si);
    }
}

// ---------------- launch -----------------------------------------------------
extern "C" void kernel_launch(void* const* d_in, const int* in_sizes, int n_in,
                              void* d_out, int out_size) {
    const float* inputs    = (const float*)d_in[0];
    const float* nu_log    = (const float*)d_in[1];
    const float* theta_log = (const float*)d_in[2];
    const float* gamma_log = (const float*)d_in[3];
    const float* B_re      = (const float*)d_in[4];
    const float* B_im      = (const float*)d_in[5];
    const float* C_re      = (const float*)d_in[6];
    const float* C_im      = (const float*)d_in[7];
    const float* Dmat      = (const float*)d_in[8];
    float* out = (float*)d_out;

    float *hidden, *bcat, *w2;
    cudaGetSymbolAddress((void**)&hidden, g_hidden);
    cudaGetSymbolAddress((void**)&bcat, g_bcat);
    cudaGetSymbolAddress((void**)&w2, g_w2);

    cudaFuncSetAttribute(tf32gemm, cudaFuncAttributeMaxDynamicSharedMemorySize,
                         SMEM_BYTES);

    prep_lambda<<<1, HID>>>(nu_log, theta_log);
    prep_bcat<<<(HID * HID) / 256, 256>>>(B_re, B_im, gamma_log);
    prep_w2<<<(HID3 * HID) / 256, 256>>>(C_re, C_im, Dmat);
    copy_inputs<<<(T_LEN * HID / 4) / 256, 256>>>(inputs);

    // GEMM1: hidden[:, :2048] = inputs(rna) @ bcat   [16384,1024]x[1024,2048]
    tf32gemm<<<dim3(2048 / BN, T_LEN / BM), 256, SMEM_BYTES>>>(
        hidden + 2048, bcat, hidden, HID, HID3, 2048, HID3);

    // complex diagonal scan, in-place (tf32-rounded outputs)
    scan_ends<<<(NCHUNK * HID) / 256, 256>>>();
    scan_carries<<<HID / 256, 256>>>();
    scan_apply<<<(NCHUNK * HID) / 256, 256>>>();

    // GEMM2: out = [h_re|h_im|inputs] @ [Ct_re; -Ct_im; D]  [16384,3072]x[3072,1024]
    tf32gemm<<<dim3(HID / BN, T_LEN / BM), 256, SMEM_BYTES>>>(
        hidden, w2, out, HID3, HID3, HID, HID);
}

// round 7
// speedup vs baseline: 5.4531x; 1.5122x over previous
#include <cuda_runtime.h>
#include <cuda_fp16.h>
#include <cstdint>

#define T_LEN 16384
#define HID 1024
#define HID3 3072
#define L_CHUNK 128
#define NCHUNK 128

#define BM 128
#define BN 128
#define BK 32           // K per stage, in halves (64 bytes)
#define ASTRH 40        // row stride in halves: b32 stride 20 -> conflict-free
#define SMEM_BYTES (2 * (BM * ASTRH + BN * ASTRH) * 2)

// ---------------- scratch ----------------------------------------------------
__device__ __half g_hidden[T_LEN * HID3];   // [h_re | h_im | inputs] per row
__device__ __half g_bcat[2048 * HID];       // [n][k]: n<1024 re, else im (K-major)
__device__ __half g_w2[HID * HID3];         // [o][k]: [C_re | -C_im | D^T]
__device__ float g_lam_re[HID], g_lam_im[HID];
__device__ float g_lamL_re[HID], g_lamL_im[HID];
__device__ float g_end_re[NCHUNK * HID], g_end_im[NCHUNK * HID];
__device__ float g_carry_re[NCHUNK * HID], g_carry_im[NCHUNK * HID];

// ---------------- helpers ----------------------------------------------------
__device__ __forceinline__ void cp16(void* dst, const void* src) {
    uint32_t d = (uint32_t)__cvta_generic_to_shared(dst);
    asm volatile("cp.async.cg.shared.global [%0], [%1], 16;" :: "r"(d), "l"(src));
}
__device__ __forceinline__ void mma_f16(float* c, const uint32_t* a, const uint32_t* b) {
    asm volatile(
        "mma.sync.aligned.m16n8k16.row.col.f32.f16.f16.f32 "
        "{%0,%1,%2,%3},{%4,%5,%6,%7},{%8,%9},{%0,%1,%2,%3};"
        : "+f"(c[0]), "+f"(c[1]), "+f"(c[2]), "+f"(c[3])
        : "r"(a[0]), "r"(a[1]), "r"(a[2]), "r"(a[3]), "r"(b[0]), "r"(b[1]));
}
__device__ __forceinline__ void store2(float* p, float x, float y) {
    *(float2*)p = make_float2(x, y);
}
__device__ __forceinline__ void store2(__half* p, float x, float y) {
    *(__half2*)p = __floats2half2_rn(x, y);
}

// ---------------- prep -------------------------------------------------------
__global__ void prep_lambda(const float* __restrict__ nu_log,
                            const float* __restrict__ theta_log) {
    int h = threadIdx.x;
    float a = -expf(nu_log[h]);
    float b = expf(theta_log[h]);
    float m = expf(a);
    g_lam_re[h] = m * cosf(b);
    g_lam_im[h] = m * sinf(b);
    double aL = (double)a * (double)L_CHUNK;
    double bL = (double)b * (double)L_CHUNK;
    double mL = exp(aL);
    g_lamL_re[h] = (float)(mL * cos(bL));
    g_lamL_im[h] = (float)(mL * sin(bL));
}

// bcat[n][k] = B[k][n] * exp(gamma[k])  (tile transpose, fused re/im)
__global__ void prep_bcat(const float* __restrict__ B_re,
                          const float* __restrict__ B_im,
                          const float* __restrict__ gamma_log) {
    __shared__ float tr[32][33], ti[32][33];
    int kb = blockIdx.y * 32, nb = blockIdx.x * 32;
    int tx = threadIdx.x;
    for (int r = threadIdx.y; r < 32; r += 8) {
        int k = kb + r;
        float g = expf(gamma_log[k]);
        tr[r][tx] = B_re[(size_t)k * HID + nb + tx] * g;
        ti[r][tx] = B_im[(size_t)k * HID + nb + tx] * g;
    }
    __syncthreads();
    for (int r = threadIdx.y; r < 32; r += 8) {
        int n = nb + r;
        g_bcat[(size_t)n * HID + kb + tx]          = __float2half_rn(tr[tx][r]);
        g_bcat[(size_t)(n + 1024) * HID + kb + tx] = __float2half_rn(ti[tx][r]);
    }
}

// w2[o][k], k<1024: C_re[o][k]; k<2048: -C_im[o][k-1024]  (coalesced copy)
__global__ void prep_w2_c(const float* __restrict__ C_re,
                          const float* __restrict__ C_im) {
    int idx = blockIdx.x * blockDim.x + threadIdx.x;   // 0 .. 1024*2048-1
    int o = idx >> 11, k = idx & 2047;
    float v = (k < 1024) ? C_re[(size_t)o * HID + k]
                         : -C_im[(size_t)o * HID + (k - 1024)];
    g_w2[(size_t)o * HID3 + k] = __float2half_rn(v);
}

// w2[o][2048+j] = D[j][o]  (tile transpose)
__global__ void prep_w2_d(const float* __restrict__ D) {
    __shared__ float td[32][33];
    int jb = blockIdx.y * 32, ob = blockIdx.x * 32;
    int tx = threadIdx.x;
    for (int r = threadIdx.y; r < 32; r += 8)
        td[r][tx] = D[(size_t)(jb + r) * HID + ob + tx];
    __syncthreads();
    for (int r = threadIdx.y; r < 32; r += 8)
        g_w2[(size_t)(ob + r) * HID3 + 2048 + jb + tx] = __float2half_rn(td[tx][r]);
}

__global__ void copy_inputs(const float* __restrict__ inputs) {
    int idx = blockIdx.x * blockDim.x + threadIdx.x;   // 8 floats per thread
    int row = idx >> 7, c8 = idx & 127;
    const float4* in4 = (const float4*)inputs;
    float4 v0 = in4[(size_t)row * 256 + c8 * 2];
    float4 v1 = in4[(size_t)row * 256 + c8 * 2 + 1];
    __half2 h0 = __floats2half2_rn(v0.x, v0.y);
    __half2 h1 = __floats2half2_rn(v0.z, v0.w);
    __half2 h2 = __floats2half2_rn(v1.x, v1.y);
    __half2 h3 = __floats2half2_rn(v1.z, v1.w);
    uint4 u = make_uint4(*(uint32_t*)&h0, *(uint32_t*)&h1,
                         *(uint32_t*)&h2, *(uint32_t*)&h3);
    *(uint4*)&g_hidden[(size_t)row * HID3 + 2048 + c8 * 8] = u;
}

// ---------------- FP16 tensor-core GEMM --------------------------------------
// C[M,N] = A[M,K] @ Bt[N,K]^T. A row-major halves (lda), Bt K-major rows (ldb).
template <typename OutT>
__global__ __launch_bounds__(256, 2)
void h16gemm(const __half* __restrict__ A, const __half* __restrict__ Bt,
             OutT* __restrict__ C, int K, int lda, int ldb, int ldc) {
    extern __shared__ __half smem[];
    __half (*As)[ASTRH] = (__half (*)[ASTRH])smem;                       // [2*BM]
    __half (*Bs)[ASTRH] = (__half (*)[ASTRH])(smem + 2 * BM * ASTRH);    // [2*BN]

    const int tid = threadIdx.x;
    const int bm = blockIdx.y * BM;
    const int bn = blockIdx.x * BN;

    const int lane = tid & 31, wid = tid >> 5;
    const int wm = (wid >> 2) * 64;
    const int wn = (wid & 3) * 32;
    const int g = lane >> 2, t = lane & 3;

    float acc[4][4][4];
#pragma unroll
    for (int mt = 0; mt < 4; mt++)
#pragma unroll
        for (int nt = 0; nt < 4; nt++)
#pragma unroll
            for (int i = 0; i < 4; i++) acc[mt][nt][i] = 0.f;

    const int niter = K / BK;

    // 512 cp16 per operand tile / 256 threads = 2 each; row = j>>2, c8 = j&3
#define LOAD_STAGE(buf, it)                                                   \
    {                                                                         \
        _Pragma("unroll")                                                     \
        for (int tt = 0; tt < 2; tt++) {                                      \
            int j = tid + tt * 256;                                           \
            int row = j >> 2, c8 = j & 3;                                     \
            cp16(&As[(buf) * BM + row][c8 * 8],                               \
                 A + (size_t)(bm + row) * lda + (it) * BK + c8 * 8);          \
        }                                                                     \
        _Pragma("unroll")                                                     \
        for (int tt = 0; tt < 2; tt++) {                                      \
            int j = tid + tt * 256;                                           \
            int row = j >> 2, c8 = j & 3;                                     \
            cp16(&Bs[(buf) * BN + row][c8 * 8],                               \
                 Bt + (size_t)(bn + row) * ldb + (it) * BK + c8 * 8);         \
        }                                                                     \
        asm volatile("cp.async.commit_group;");                               \
    }

    LOAD_STAGE(0, 0)

    for (int i = 0; i < niter; i++) {
        if (i + 1 < niter) {
            LOAD_STAGE((i + 1) & 1, i + 1)
            asm volatile("cp.async.wait_group 1;");
        } else {
            asm volatile("cp.async.wait_group 0;");
        }
        __syncthreads();

        const int abase = (i & 1) * BM;
        const int bbase = (i & 1) * BN;
#pragma unroll
        for (int ks = 0; ks < 2; ks++) {
            const int k16 = ks * 16;
            uint32_t af[4][4], bf[4][2];
#pragma unroll
            for (int mt = 0; mt < 4; mt++) {
                const uint32_t* ap =
                    (const uint32_t*)&As[abase + wm + mt * 16 + g][k16 + 2 * t];
                af[mt][0] = ap[0];
                af[mt][1] = ap[8 * ASTRH / 2];
                af[mt][2] = ap[4];
                af[mt][3] = ap[8 * ASTRH / 2 + 4];
            }
#pragma unroll
            for (int nt = 0; nt < 4; nt++) {
                const uint32_t* bp =
                    (const uint32_t*)&Bs[bbase + wn + nt * 8 + g][k16 + 2 * t];
                bf[nt][0] = bp[0];
                bf[nt][1] = bp[4];
            }
#pragma unroll
            for (int mt = 0; mt < 4; mt++)
#pragma unroll
                for (int nt = 0; nt < 4; nt++)
                    mma_f16(acc[mt][nt], af[mt], bf[nt]);
        }
        __syncthreads();
    }
#undef LOAD_STAGE

    OutT* Cb = C + (size_t)(bm + wm) * ldc + bn + wn;
#pragma unroll
    for (int mt = 0; mt < 4; mt++) {
#pragma unroll
        for (int nt = 0; nt < 4; nt++) {
            const int r0 = mt * 16 + g;
            const int c0 = nt * 8 + t * 2;
            store2(&Cb[(size_t)r0 * ldc + c0], acc[mt][nt][0], acc[mt][nt][1]);
            store2(&Cb[(size_t)(r0 + 8) * ldc + c0], acc[mt][nt][2], acc[mt][nt][3]);
        }
    }
}

// ---------------- chunked complex scan (g_hidden cols 0..2047, fp16 I/O) -----
__global__ void scan_ends() {
    int gidx = blockIdx.x * blockDim.x + threadIdx.x;
    int h = gidx & 1023, chunk = gidx >> 10;
    float lr = g_lam_re[h], li = g_lam_im[h];
    float sr = 0.f, si = 0.f;
    size_t base = (size_t)chunk * L_CHUNK * HID3 + h;
#pragma unroll 4
    for (int tt = 0; tt < L_CHUNK; tt++) {
        float br = __half2float(g_hidden[base + (size_t)tt * HID3]);
        float bi = __half2float(g_hidden[base + (size_t)tt * HID3 + 1024]);
        float nr = fmaf(lr, sr, fmaf(-li, si, br));
        float ni = fmaf(lr, si, fmaf(li, sr, bi));
        sr = nr; si = ni;
    }
    g_end_re[chunk * HID + h] = sr;
    g_end_im[chunk * HID + h] = si;
}

__global__ void scan_carries() {
    int h = blockIdx.x * blockDim.x + threadIdx.x;
    float lr = g_lamL_re[h], li = g_lamL_im[h];
    float cr = 0.f, ci = 0.f;
    for (int c = 0; c < NCHUNK; c++) {
        g_carry_re[c * HID + h] = cr;
        g_carry_im[c * HID + h] = ci;
        float er = g_end_re[c * HID + h], ei = g_end_im[c * HID + h];
        float nr = fmaf(lr, cr, fmaf(-li, ci, er));
        float ni = fmaf(lr, ci, fmaf(li, cr, ei));
        cr = nr; ci = ni;
    }
}

__global__ void scan_apply() {
    int gidx = blockIdx.x * blockDim.x + threadIdx.x;
    int h = gidx & 1023, chunk = gidx >> 10;
    float lr = g_lam_re[h], li = g_lam_im[h];
    float sr = g_carry_re[chunk * HID + h];
    float si = g_carry_im[chunk * HID + h];
    size_t base = (size_t)chunk * L_CHUNK * HID3 + h;
#pragma unroll 4
    for (int tt = 0; tt < L_CHUNK; tt++) {
        float br = __half2float(g_hidden[base + (size_t)tt * HID3]);
        float bi = __half2float(g_hidden[base + (size_t)tt * HID3 + 1024]);
        float nr = fmaf(lr, sr, fmaf(-li, si, br));
        float ni = fmaf(lr, si, fmaf(li, sr, bi));
        sr = nr; si = ni;
        g_hidden[base + (size_t)tt * HID3]        = __float2half_rn(sr);
        g_hidden[base + (size_t)tt * HID3 + 1024] = __float2half_rn(si);
    }
}

// ---------------- launch -----------------------------------------------------
extern "C" void kernel_launch(void* const* d_in, const int* in_sizes, int n_in,
                              void* d_out, int out_size) {
    const float* inputs    = (const float*)d_in[0];
    const float* nu_log    = (const float*)d_in[1];
    const float* theta_log = (const float*)d_in[2];
    const float* gamma_log = (const float*)d_in[3];
    const float* B_re      = (const float*)d_in[4];
    const float* B_im      = (const float*)d_in[5];
    const float* C_re      = (const float*)d_in[6];
    const float* C_im      = (const float*)d_in[7];
    const float* Dmat      = (const float*)d_in[8];
    float* out = (float*)d_out;

    __half *hidden, *bcat, *w2;
    cudaGetSymbolAddress((void**)&hidden, g_hidden);
    cudaGetSymbolAddress((void**)&bcat, g_bcat);
    cudaGetSymbolAddress((void**)&w2, g_w2);

    cudaFuncSetAttribute(h16gemm<__half>,
                         cudaFuncAttributeMaxDynamicSharedMemorySize, SMEM_BYTES);
    cudaFuncSetAttribute(h16gemm<float>,
                         cudaFuncAttributeMaxDynamicSharedMemorySize, SMEM_BYTES);

    prep_lambda<<<1, HID>>>(nu_log, theta_log);
    prep_bcat<<<dim3(32, 32), dim3(32, 8)>>>(B_re, B_im, gamma_log);
    prep_w2_c<<<(HID * 2048) / 256, 256>>>(C_re, C_im);
    prep_w2_d<<<dim3(32, 32), dim3(32, 8)>>>(Dmat);
    copy_inputs<<<(T_LEN * HID / 8) / 256, 256>>>(inputs);

    // GEMM1: hidden[:, :2048] = inputs(h16) @ bcat^T   [16384,1024]x[2048,1024]^T
    h16gemm<__half><<<dim3(2048 / BN, T_LEN / BM), 256, SMEM_BYTES>>>(
        hidden + 2048, bcat, hidden, HID, HID3, HID, HID3);

    // complex diagonal scan, in-place
    scan_ends<<<(NCHUNK * HID) / 256, 256>>>();
    scan_carries<<<HID / 256, 256>>>();
    scan_apply<<<(NCHUNK * HID) / 256, 256>>>();

    // GEMM2: out = [h_re|h_im|inputs] @ w2^T   [16384,3072]x[1024,3072]^T
    h16gemm<float><<<dim3(HID / BN, T_LEN / BM), 256, SMEM_BYTES>>>(
        hidden, w2, out, HID3, HID3, HID3, HID);
}